// round 13
// baseline (speedup 1.0000x reference)
#include <cuda_runtime.h>
#include <cstdint>

// Problem constants (fixed shapes from setup_inputs)
#define TT 64
#define BB 4096
#define DD 32
#define HH 5
#define GG 20      // 4*H gates
#define VV 10
#define IN 128

#define BLK 256
#define NCHUNK (BB / BLK)           // 16 b-chunks

// Per-b precomputed terms (transposed [g][B] for coalesced access), L2-resident.
__device__ float g_hb0[GG * BB];
__device__ float g_hb1[GG * BB];
__device__ float g_c0[HH * BB];
__device__ float g_c1[HH * BB];
__device__ float g_lut[3 * VV * GG];   // [j][v][g] embedding->gate LUT

// ---- fast activations: HW tanh (sm_75+), sigmoid via tanh identity ----
__device__ __forceinline__ float tanh_fast(float v) {
    float r;
    asm("tanh.approx.f32 %0, %1;" : "=f"(r) : "f"(v));
    return r;
}
__device__ __forceinline__ float sigm(float v) {
    return fmaf(0.5f, tanh_fast(0.5f * v), 0.5f);
}

// ---------------------------------------------------------------------------
// Kernel 1: precompute. Blocks 0..63: (b, quarter) threads computing 5 gates
// of hb0 and 5 of hb1 each + cell transpose. Block 64: the embedding LUT.
// (exact math here — runs once, negligible cost)
// ---------------------------------------------------------------------------
__global__ void prep_kernel(const float* __restrict__ hidden,
                            const float* __restrict__ cell,
                            const float* __restrict__ embed,
                            const float* __restrict__ W_ih0,
                            const float* __restrict__ W_hh0,
                            const float* __restrict__ b_ih0,
                            const float* __restrict__ b_hh0,
                            const float* __restrict__ W_hh1,
                            const float* __restrict__ b_ih1,
                            const float* __restrict__ b_hh1) {
    if (blockIdx.x < 64) {
        int idx = blockIdx.x * BLK + threadIdx.x;
        int b = idx >> 2;             // 0..4095
        int q = idx & 3;              // gate quarter: gates [5q, 5q+5)
        float h0[HH], h1[HH];
#pragma unroll
        for (int k = 0; k < HH; k++) {
            h0[k] = hidden[b * HH + k];
            h1[k] = hidden[BB * HH + b * HH + k];
        }
#pragma unroll
        for (int j = 0; j < 5; j++) {
            int g = q * 5 + j;
            float s0 = b_ih0[g] + b_hh0[g];
            float s1 = b_ih1[g] + b_hh1[g];
#pragma unroll
            for (int k = 0; k < HH; k++) {
                s0 = fmaf(h0[k], W_hh0[g * HH + k], s0);
                s1 = fmaf(h1[k], W_hh1[g * HH + k], s1);
            }
            g_hb0[g * BB + b] = s0;
            g_hb1[g * BB + b] = s1;
        }
        if (q == 0) {
#pragma unroll
            for (int k = 0; k < HH; k++) {
                g_c0[k * BB + b] = cell[b * HH + k];
                g_c1[k * BB + b] = cell[BB * HH + b * HH + k];
            }
        }
    } else {
        for (int i = threadIdx.x; i < 3 * VV * GG; i += BLK) {
            int j = i / (VV * GG);
            int r = i - j * (VV * GG);
            int v = r / GG;
            int g = r - v * GG;
            const float* e = embed + v * DD;
            const float* w = W_ih0 + g * IN + DD + DD * j;
            float s = 0.0f;
#pragma unroll
            for (int k = 0; k < DD; k++) s = fmaf(e[k], w[k], s);
            g_lut[i] = s;   // layout [j][v][g]
        }
    }
}

// ---------------------------------------------------------------------------
// Kernel 2: main. One thread per (t, b). IPT=1, 64-reg cap -> 4 CTAs/SM.
// Weight LDS.128 are warp-uniform broadcasts; dec_x loads fully coalesced.
// Activations use HW tanh.approx (rel_err ~4e-6, threshold 1e-3).
//   blockIdx.x = b-chunk (16), blockIdx.y = t (64). 256 threads.
// ---------------------------------------------------------------------------
__global__ void __launch_bounds__(BLK, 4)
decoder_kernel(const float* __restrict__ dec_x,
               const int*   __restrict__ id1,
               const int*   __restrict__ id2,
               const int*   __restrict__ id3,
               const float* __restrict__ W_ih0,
               const float* __restrict__ W_ih1,
               float* __restrict__ out) {
    __shared__ __align__(16) float sWa[GG * DD];        // W_ih0[:,0:32] (f4 rows)
    __shared__ __align__(16) float sLut[3 * VV * GG];   // [j][v][g], 80B rows
    __shared__ __align__(16) float sW1t[HH * GG];       // W_ih1^T [k][g]
    __shared__ __align__(16) float sOut[BLK * HH];      // output staging

    const int tid = threadIdx.x;

    // ---- cooperative shared fill (copies only; LUT precomputed) ----
    for (int i = tid; i < GG * DD; i += BLK) {
        int g = i >> 5, k = i & 31;
        sWa[i] = W_ih0[g * IN + k];
    }
    for (int i = tid; i < HH * GG; i += BLK) {
        int k = i / GG, g = i - k * GG;
        sW1t[i] = W_ih1[g * HH + k];
    }
    for (int i = tid; i < 3 * VV * GG; i += BLK) sLut[i] = g_lut[i];
    __syncthreads();

    const int t  = blockIdx.y;
    const int b  = blockIdx.x * BLK + tid;
    const int tb = t * BB + b;

    // ---- init acc with hb0 (coalesced LDG, L2-resident) ----
    float acc[GG];
#pragma unroll
    for (int g = 0; g < GG; g++) acc[g] = g_hb0[g * BB + b];

    // ---- embedding LUT adds (f4 over g, 5 per row) ----
    {
        const int i1 = id1[tb], i2 = id2[tb], i3 = id3[tb];
        const float4* l1 = (const float4*)(sLut + (0 * VV + i1) * GG);
        const float4* l2 = (const float4*)(sLut + (1 * VV + i2) * GG);
        const float4* l3 = (const float4*)(sLut + (2 * VV + i3) * GG);
#pragma unroll
        for (int q = 0; q < GG / 4; q++) {
            float4 a = l1[q], c = l2[q], d = l3[q];
            acc[4 * q + 0] += a.x + c.x + d.x;
            acc[4 * q + 1] += a.y + c.y + d.y;
            acc[4 * q + 2] += a.z + c.z + d.z;
            acc[4 * q + 3] += a.w + c.w + d.w;
        }
    }

    // ---- dec_x @ Wa^T : k-outer, one x float4 live; w LDS.128 broadcast ----
    {
        const float4* xp = (const float4*)(dec_x + (size_t)tb * DD);
#pragma unroll
        for (int q = 0; q < DD / 4; q++) {
            float4 x = xp[q];
            const float4* wp = (const float4*)sWa + q;   // stride DD/4 per gate
#pragma unroll
            for (int g = 0; g < GG; g++) {
                float4 w = wp[g * (DD / 4)];
                acc[g] = fmaf(x.x, w.x, fmaf(x.y, w.y,
                         fmaf(x.z, w.z, fmaf(x.w, w.w, acc[g]))));
            }
        }
    }

    // ---- LSTM cell 0 (gate order i, f, g, o) ----
    float h1[HH];
#pragma unroll
    for (int k = 0; k < HH; k++) {
        float ig = sigm(acc[k]);
        float fg = sigm(acc[HH + k]);
        float gg = tanh_fast(acc[2 * HH + k]);
        float og = sigm(acc[3 * HH + k]);
        float c  = fmaf(fg, g_c0[k * BB + b], ig * gg);
        h1[k] = og * tanh_fast(c);
    }

    // ---- layer-1 gates: hb1 + h1 @ W_ih1^T (k-outer, f4 broadcast) ----
    float a1[GG];
#pragma unroll
    for (int g = 0; g < GG; g++) a1[g] = g_hb1[g * BB + b];
#pragma unroll
    for (int k = 0; k < HH; k++) {
        const float4* wp = (const float4*)(sW1t + k * GG);
        float hv = h1[k];
#pragma unroll
        for (int q = 0; q < GG / 4; q++) {
            float4 w = wp[q];
            a1[4 * q + 0] = fmaf(hv, w.x, a1[4 * q + 0]);
            a1[4 * q + 1] = fmaf(hv, w.y, a1[4 * q + 1]);
            a1[4 * q + 2] = fmaf(hv, w.z, a1[4 * q + 2]);
            a1[4 * q + 3] = fmaf(hv, w.w, a1[4 * q + 3]);
        }
    }

    // ---- LSTM cell 1 -> staged output ----
#pragma unroll
    for (int k = 0; k < HH; k++) {
        float ig = sigm(a1[k]);
        float fg = sigm(a1[HH + k]);
        float gg = tanh_fast(a1[2 * HH + k]);
        float og = sigm(a1[3 * HH + k]);
        float c  = fmaf(fg, g_c1[k * BB + b], ig * gg);
        sOut[tid * HH + k] = og * tanh_fast(c);
    }
    __syncthreads();

    // ---- coalesced store of the block's [256, 5] output slab ----
    float* ob = out + (size_t)t * BB * HH + (size_t)blockIdx.x * BLK * HH;
    for (int i = tid; i < BLK * HH; i += BLK) ob[i] = sOut[i];
}

// ---------------------------------------------------------------------------
// Launch
// Input order: 0 horizon, 1 hidden, 2 cell, 3 dec_x, 4 mote_id_cat,
// 5 fault_type_cat, 6 mote_fault_cat, 7 mote_embed, 8 W_ih0, 9 W_hh0,
// 10 b_ih0, 11 b_hh0, 12 W_ih1, 13 W_hh1, 14 b_ih1, 15 b_hh1
// ---------------------------------------------------------------------------
extern "C" void kernel_launch(void* const* d_in, const int* in_sizes, int n_in,
                              void* d_out, int out_size) {
    const float* hidden = (const float*)d_in[1];
    const float* cell   = (const float*)d_in[2];
    const float* dec_x  = (const float*)d_in[3];
    const int*   id1    = (const int*)d_in[4];
    const int*   id2    = (const int*)d_in[5];
    const int*   id3    = (const int*)d_in[6];
    const float* embed  = (const float*)d_in[7];
    const float* W_ih0  = (const float*)d_in[8];
    const float* W_hh0  = (const float*)d_in[9];
    const float* b_ih0  = (const float*)d_in[10];
    const float* b_hh0  = (const float*)d_in[11];
    const float* W_ih1  = (const float*)d_in[12];
    const float* W_hh1  = (const float*)d_in[13];
    const float* b_ih1  = (const float*)d_in[14];
    const float* b_hh1  = (const float*)d_in[15];
    float* out = (float*)d_out;

    prep_kernel<<<65, BLK>>>(hidden, cell, embed, W_ih0, W_hh0, b_ih0, b_hh0,
                             W_hh1, b_ih1, b_hh1);

    dim3 grid(NCHUNK, TT);
    decoder_kernel<<<grid, BLK>>>(dec_x, id1, id2, id3, W_ih0, W_ih1, out);
}

// round 14
// speedup vs baseline: 1.1182x; 1.1182x over previous
#include <cuda_runtime.h>
#include <cstdint>

// Problem constants (fixed shapes from setup_inputs)
#define TT 64
#define BB 4096
#define DD 32
#define HH 5
#define GG 20      // 4*H gates
#define VV 10
#define IN 128

#define BLK 256
#define NCHUNK (BB / BLK)           // 16 b-chunks
#define TGRID (TT / 2)              // 32 (two t per thread: t and t+32)

// Per-b precomputed terms (transposed [g][B] for coalesced access), L2-resident.
__device__ float g_hb0[GG * BB];
__device__ float g_hb1[GG * BB];
__device__ float g_c0[HH * BB];
__device__ float g_c1[HH * BB];
__device__ float g_lut[3 * VV * GG];   // [j][v][g] embedding->gate LUT

// ---- fast activations: HW tanh (sm_75+), sigmoid via tanh identity ----
__device__ __forceinline__ float tanh_fast(float v) {
    float r;
    asm("tanh.approx.f32 %0, %1;" : "=f"(r) : "f"(v));
    return r;
}
__device__ __forceinline__ float sigm(float v) {
    return fmaf(0.5f, tanh_fast(0.5f * v), 0.5f);
}

// ---------------------------------------------------------------------------
// Kernel 1: precompute. Blocks 0..63: (b, quarter) threads computing 5 gates
// of hb0 and 5 of hb1 each + cell transpose. Block 64: the embedding LUT.
// ---------------------------------------------------------------------------
__global__ void prep_kernel(const float* __restrict__ hidden,
                            const float* __restrict__ cell,
                            const float* __restrict__ embed,
                            const float* __restrict__ W_ih0,
                            const float* __restrict__ W_hh0,
                            const float* __restrict__ b_ih0,
                            const float* __restrict__ b_hh0,
                            const float* __restrict__ W_hh1,
                            const float* __restrict__ b_ih1,
                            const float* __restrict__ b_hh1) {
    if (blockIdx.x < 64) {
        int idx = blockIdx.x * BLK + threadIdx.x;
        int b = idx >> 2;             // 0..4095
        int q = idx & 3;              // gate quarter: gates [5q, 5q+5)
        float h0[HH], h1[HH];
#pragma unroll
        for (int k = 0; k < HH; k++) {
            h0[k] = hidden[b * HH + k];
            h1[k] = hidden[BB * HH + b * HH + k];
        }
#pragma unroll
        for (int j = 0; j < 5; j++) {
            int g = q * 5 + j;
            float s0 = b_ih0[g] + b_hh0[g];
            float s1 = b_ih1[g] + b_hh1[g];
#pragma unroll
            for (int k = 0; k < HH; k++) {
                s0 = fmaf(h0[k], W_hh0[g * HH + k], s0);
                s1 = fmaf(h1[k], W_hh1[g * HH + k], s1);
            }
            g_hb0[g * BB + b] = s0;
            g_hb1[g * BB + b] = s1;
        }
        if (q == 0) {
#pragma unroll
            for (int k = 0; k < HH; k++) {
                g_c0[k * BB + b] = cell[b * HH + k];
                g_c1[k * BB + b] = cell[BB * HH + b * HH + k];
            }
        }
    } else {
        for (int i = threadIdx.x; i < 3 * VV * GG; i += BLK) {
            int j = i / (VV * GG);
            int r = i - j * (VV * GG);
            int v = r / GG;
            int g = r - v * GG;
            const float* e = embed + v * DD;
            const float* w = W_ih0 + g * IN + DD + DD * j;
            float s = 0.0f;
#pragma unroll
            for (int k = 0; k < DD; k++) s = fmaf(e[k], w[k], s);
            g_lut[i] = s;   // layout [j][v][g]
        }
    }
}

// ---------------------------------------------------------------------------
// Kernel 2: main. One thread per (b, {t, t+32}) — the two time steps are
// REGISTER-INTERLEAVED: one k-loop feeds both items from each weight LDS.128,
// and the per-b terms (hb0/hb1/c0/c1) are loaded once for both.
//   blockIdx.x = b-chunk (16), blockIdx.y = t0 (32). 256 threads, 64-reg cap.
// ---------------------------------------------------------------------------
__global__ void __launch_bounds__(BLK, 4)
decoder_kernel(const float* __restrict__ dec_x,
               const int*   __restrict__ id1,
               const int*   __restrict__ id2,
               const int*   __restrict__ id3,
               const float* __restrict__ W_ih0,
               const float* __restrict__ W_ih1,
               float* __restrict__ out) {
    __shared__ __align__(16) float sWa[GG * DD];        // W_ih0[:,0:32] (f4 rows)
    __shared__ __align__(16) float sLut[3 * VV * GG];   // [j][v][g], 80B rows
    __shared__ __align__(16) float sW1t[HH * GG];       // W_ih1^T [k][g]
    __shared__ __align__(16) float sOut[2 * BLK * HH];  // both items' staging

    const int tid = threadIdx.x;

    // ---- cooperative shared fill (copies only; LUT precomputed) ----
    for (int i = tid; i < GG * DD; i += BLK) {
        int g = i >> 5, k = i & 31;
        sWa[i] = W_ih0[g * IN + k];
    }
    for (int i = tid; i < HH * GG; i += BLK) {
        int k = i / GG, g = i - k * GG;
        sW1t[i] = W_ih1[g * HH + k];
    }
    for (int i = tid; i < 3 * VV * GG; i += BLK) sLut[i] = g_lut[i];
    __syncthreads();

    const int b   = blockIdx.x * BLK + tid;
    const int t0  = blockIdx.y;                 // item 0: t0, item 1: t0+32
    const int tbA = t0 * BB + b;
    const int tbB = (t0 + TGRID) * BB + b;

    // ---- init both accumulators with hb0 (loaded ONCE) ----
    float acc[2][GG];
#pragma unroll
    for (int g = 0; g < GG; g++) {
        float h = g_hb0[g * BB + b];
        acc[0][g] = h;
        acc[1][g] = h;
    }

    // ---- embedding LUT adds per item (f4 over g) ----
#pragma unroll
    for (int it = 0; it < 2; it++) {
        const int tb = (it == 0) ? tbA : tbB;
        const int i1 = id1[tb], i2 = id2[tb], i3 = id3[tb];
        const float4* l1 = (const float4*)(sLut + (0 * VV + i1) * GG);
        const float4* l2 = (const float4*)(sLut + (1 * VV + i2) * GG);
        const float4* l3 = (const float4*)(sLut + (2 * VV + i3) * GG);
#pragma unroll
        for (int q = 0; q < GG / 4; q++) {
            float4 a = l1[q], c = l2[q], d = l3[q];
            acc[it][4 * q + 0] += a.x + c.x + d.x;
            acc[it][4 * q + 1] += a.y + c.y + d.y;
            acc[it][4 * q + 2] += a.z + c.z + d.z;
            acc[it][4 * q + 3] += a.w + c.w + d.w;
        }
    }

    // ---- dual-t GEMM: each weight LDS.128 feeds both items (8 FMA/load) ----
    {
        const float4* xpA = (const float4*)(dec_x + (size_t)tbA * DD);
        const float4* xpB = (const float4*)(dec_x + (size_t)tbB * DD);
#pragma unroll
        for (int q = 0; q < DD / 4; q++) {
            float4 xa = xpA[q];
            float4 xb = xpB[q];
            const float4* wp = (const float4*)sWa + q;   // stride DD/4 per gate
#pragma unroll
            for (int g = 0; g < GG; g++) {
                float4 w = wp[g * (DD / 4)];
                acc[0][g] = fmaf(xa.x, w.x, fmaf(xa.y, w.y,
                            fmaf(xa.z, w.z, fmaf(xa.w, w.w, acc[0][g]))));
                acc[1][g] = fmaf(xb.x, w.x, fmaf(xb.y, w.y,
                            fmaf(xb.z, w.z, fmaf(xb.w, w.w, acc[1][g]))));
            }
        }
    }

    // ---- LSTM cell 0 for BOTH items (c0 loaded once); frees acc -> h1 ----
    float h1[2][HH];
#pragma unroll
    for (int k = 0; k < HH; k++) {
        float cc = g_c0[k * BB + b];
#pragma unroll
        for (int it = 0; it < 2; it++) {
            float ig = sigm(acc[it][k]);
            float fg = sigm(acc[it][HH + k]);
            float gg = tanh_fast(acc[it][2 * HH + k]);
            float og = sigm(acc[it][3 * HH + k]);
            float c  = fmaf(fg, cc, ig * gg);
            h1[it][k] = og * tanh_fast(c);
        }
    }

    // ---- layer-1 gates for both items (hb1 + sW1t loaded once) ----
    float a1[2][GG];
#pragma unroll
    for (int g = 0; g < GG; g++) {
        float h = g_hb1[g * BB + b];
        a1[0][g] = h;
        a1[1][g] = h;
    }
#pragma unroll
    for (int k = 0; k < HH; k++) {
        const float4* wp = (const float4*)(sW1t + k * GG);
#pragma unroll
        for (int q = 0; q < GG / 4; q++) {
            float4 w = wp[q];
#pragma unroll
            for (int it = 0; it < 2; it++) {
                float hv = h1[it][k];
                a1[it][4 * q + 0] = fmaf(hv, w.x, a1[it][4 * q + 0]);
                a1[it][4 * q + 1] = fmaf(hv, w.y, a1[it][4 * q + 1]);
                a1[it][4 * q + 2] = fmaf(hv, w.z, a1[it][4 * q + 2]);
                a1[it][4 * q + 3] = fmaf(hv, w.w, a1[it][4 * q + 3]);
            }
        }
    }

    // ---- LSTM cell 1 for both items (c1 loaded once) -> staged output ----
#pragma unroll
    for (int k = 0; k < HH; k++) {
        float cc = g_c1[k * BB + b];
#pragma unroll
        for (int it = 0; it < 2; it++) {
            float ig = sigm(a1[it][k]);
            float fg = sigm(a1[it][HH + k]);
            float gg = tanh_fast(a1[it][2 * HH + k]);
            float og = sigm(a1[it][3 * HH + k]);
            float c  = fmaf(fg, cc, ig * gg);
            sOut[it * BLK * HH + tid * HH + k] = og * tanh_fast(c);
        }
    }
    __syncthreads();

    // ---- coalesced store of both [256, 5] output slabs ----
    {
        float* obA = out + (size_t)t0 * BB * HH + (size_t)blockIdx.x * BLK * HH;
        float* obB = out + (size_t)(t0 + TGRID) * BB * HH
                         + (size_t)blockIdx.x * BLK * HH;
        for (int i = tid; i < BLK * HH; i += BLK) {
            obA[i] = sOut[i];
            obB[i] = sOut[BLK * HH + i];
        }
    }
}

// ---------------------------------------------------------------------------
// Launch
// Input order: 0 horizon, 1 hidden, 2 cell, 3 dec_x, 4 mote_id_cat,
// 5 fault_type_cat, 6 mote_fault_cat, 7 mote_embed, 8 W_ih0, 9 W_hh0,
// 10 b_ih0, 11 b_hh0, 12 W_ih1, 13 W_hh1, 14 b_ih1, 15 b_hh1
// ---------------------------------------------------------------------------
extern "C" void kernel_launch(void* const* d_in, const int* in_sizes, int n_in,
                              void* d_out, int out_size) {
    const float* hidden = (const float*)d_in[1];
    const float* cell   = (const float*)d_in[2];
    const float* dec_x  = (const float*)d_in[3];
    const int*   id1    = (const int*)d_in[4];
    const int*   id2    = (const int*)d_in[5];
    const int*   id3    = (const int*)d_in[6];
    const float* embed  = (const float*)d_in[7];
    const float* W_ih0  = (const float*)d_in[8];
    const float* W_hh0  = (const float*)d_in[9];
    const float* b_ih0  = (const float*)d_in[10];
    const float* b_hh0  = (const float*)d_in[11];
    const float* W_ih1  = (const float*)d_in[12];
    const float* W_hh1  = (const float*)d_in[13];
    const float* b_ih1  = (const float*)d_in[14];
    const float* b_hh1  = (const float*)d_in[15];
    float* out = (float*)d_out;

    prep_kernel<<<65, BLK>>>(hidden, cell, embed, W_ih0, W_hh0, b_ih0, b_hh0,
                             W_hh1, b_ih1, b_hh1);

    dim3 grid(NCHUNK, TGRID);
    decoder_kernel<<<grid, BLK>>>(dec_x, id1, id2, id3, W_ih0, W_ih1, out);
}